// round 3
// baseline (speedup 1.0000x reference)
#include <cuda_runtime.h>

#define NPIX 4096
#define BT 2

// 50*log2(e), 25*log2(e), log2(e)
#define C50F   72.13475204444817f
#define C25F   36.067376022224085f
#define CL2E   1.4426950408889634f

// ---------------------------------------------------------------------------
// Scratch (device globals; no allocations allowed)
// ---------------------------------------------------------------------------
// per-i record: [0] = (a0,a1,a2,|a|^2)   [1] = (fs0,fs1,fs2, L2row)
__device__ float4 g_iRec[BT][NPIX][2];
// per-j record: [0] = (u0,u1,u2, LSEcol2) [1] = (ft*log2e x3, 0) [2] = (fs0,fs1,fs2,0)
__device__ float4 g_jRec[BT][NPIX][3];

// ---------------------------------------------------------------------------
__device__ __forceinline__ float ex2f(float x) {
    float y;
    asm("ex2.approx.ftz.f32 %0, %1;" : "=f"(y) : "f"(x));
    return y;
}
__device__ __forceinline__ float sqapx(float x) {
    float y;
    asm("sqrt.approx.ftz.f32 %0, %1;" : "=f"(y) : "f"(x));
    return y;
}

// ---------------------------------------------------------------------------
// Precompute per-i / per-j records (tiny; double precision for geometry)
// ---------------------------------------------------------------------------
__global__ void k_pre(const float* __restrict__ f_tar, const float* __restrict__ f_src,
                      const float* __restrict__ Km, const float* __restrict__ Rm,
                      const float* __restrict__ tv) {
    int b = blockIdx.x;
    double Kd[9], Rd[9], td[3];
    #pragma unroll
    for (int m = 0; m < 9; m++) { Kd[m] = (double)Km[b*9+m]; Rd[m] = (double)Rm[b*9+m]; }
    #pragma unroll
    for (int m = 0; m < 3; m++) td[m] = (double)tv[b*3+m];

    double c00 = Kd[4]*Kd[8] - Kd[5]*Kd[7];
    double c10 = Kd[5]*Kd[6] - Kd[3]*Kd[8];
    double c20 = Kd[3]*Kd[7] - Kd[4]*Kd[6];
    double det = Kd[0]*c00 + Kd[1]*c10 + Kd[2]*c20;
    double id  = 1.0 / det;
    double Ki[9];
    Ki[0] = c00*id; Ki[1] = (Kd[2]*Kd[7]-Kd[1]*Kd[8])*id; Ki[2] = (Kd[1]*Kd[5]-Kd[2]*Kd[4])*id;
    Ki[3] = c10*id; Ki[4] = (Kd[0]*Kd[8]-Kd[2]*Kd[6])*id; Ki[5] = (Kd[2]*Kd[3]-Kd[0]*Kd[5])*id;
    Ki[6] = c20*id; Ki[7] = (Kd[1]*Kd[6]-Kd[0]*Kd[7])*id; Ki[8] = (Kd[0]*Kd[4]-Kd[1]*Kd[3])*id;

    double o0 = Kd[0]*td[0] + Kd[1]*td[1] + Kd[2]*td[2];
    double o1 = Kd[3]*td[0] + Kd[4]*td[1] + Kd[5]*td[2];
    double o2 = Kd[6]*td[0] + Kd[7]*td[1] + Kd[8]*td[2];
    float of0 = (float)o0, of1 = (float)o1, of2 = (float)o2;

    const float* fs = f_src + b*3*NPIX;
    const float* ft = f_tar + b*3*NPIX;

    for (int j = threadIdx.x; j < NPIX; j += blockDim.x) {
        double px = (double)(j >> 6), py = (double)(j & 63);
        double ca = Ki[0]*px + Ki[1]*py + Ki[2];
        double cb = Ki[3]*px + Ki[4]*py + Ki[5];
        double cc = Ki[6]*px + Ki[7]*py + Ki[8];
        double ra = Rd[0]*ca + Rd[1]*cb + Rd[2]*cc + td[0];
        double rb = Rd[3]*ca + Rd[4]*cb + Rd[5]*cc + td[1];
        double rc = Rd[6]*ca + Rd[7]*cb + Rd[8]*cc + td[2];
        double da = Kd[0]*ra + Kd[1]*rb + Kd[2]*rc - o0;
        double db = Kd[3]*ra + Kd[4]*rb + Kd[5]*rc - o1;
        double dc = Kd[6]*ra + Kd[7]*rb + Kd[8]*rc - o2;
        double inv = 1.0 / sqrt(da*da + db*db + dc*dc);
        float u0 = (float)(da*inv), u1 = (float)(db*inv), u2 = (float)(dc*inv);

        float t0 = ft[j], t1 = ft[NPIX + j], t2 = ft[2*NPIX + j];
        float s0 = fs[j], s1 = fs[NPIX + j], s2 = fs[2*NPIX + j];
        g_jRec[b][j][0] = make_float4(u0, u1, u2, 0.f);
        g_jRec[b][j][1] = make_float4(t0*CL2E, t1*CL2E, t2*CL2E, 0.f);
        g_jRec[b][j][2] = make_float4(s0, s1, s2, 0.f);

        float a0 = s0 - of0, a1 = s1 - of1, a2 = s2 - of2;
        float na2 = (float)((double)a0*a0 + (double)a1*a1 + (double)a2*a2);
        g_iRec[b][j][0] = make_float4(a0, a1, a2, na2);
        g_iRec[b][j][1] = make_float4(s0, s1, s2, 0.f);
    }
}

// ---------------------------------------------------------------------------
// Pass 1: row LSE of s_ij. Lane owns a row; warp w sweeps j-chunk [w*128,+128).
// Sweep A: min (a.u)^2 (exact row max of d, no MUFU). Sweep B: sum of ex2.
// ---------------------------------------------------------------------------
__global__ void __launch_bounds__(1024, 2) k_rowstats() {
    __shared__ float sMrg[32][33];
    int b = blockIdx.x;
    int lane = threadIdx.x & 31, w = threadIdx.x >> 5;
    int row = blockIdx.y * 32 + lane;

    float4 A = g_iRec[b][row][0];
    const float4* J0 = &g_jRec[b][w * 128][0];

    float m = 3.4e38f;
    #pragma unroll 4
    for (int k = 0; k < 128; k++) {
        float4 U = __ldg(J0 + k * 3);
        float d = fmaf(A.x, U.x, fmaf(A.y, U.y, A.z * U.z));
        m = fminf(m, d * d);
    }
    sMrg[lane][w] = m;
    __syncthreads();
    float mm = 3.4e38f;
    #pragma unroll
    for (int k = 0; k < 32; k++) mm = fminf(mm, sMrg[lane][k]);
    float cM = sqapx(fmaxf(A.w - mm, 0.f)) * C50F;   // max_j d * 50*log2e
    __syncthreads();

    float s = 0.f;
    #pragma unroll 2
    for (int k = 0; k < 128; k++) {
        float4 U = __ldg(J0 + k * 3);
        float d = fmaf(A.x, U.x, fmaf(A.y, U.y, A.z * U.z));
        float q = fmaxf(fmaf(-d, d, A.w), 0.f);
        s += ex2f(fmaf(sqapx(q), C50F, -cM));
    }
    sMrg[lane][w] = s;
    __syncthreads();
    if (w == 0) {
        float S = 0.f;
        #pragma unroll
        for (int k = 0; k < 32; k++) S += sMrg[lane][k];
        ((float*)&g_iRec[b][row][1])[3] = (cM - C25F) + log2f(S);
    }
}

// ---------------------------------------------------------------------------
// Pass 2: column log2-sum of exp2(AW*log2e). Lane owns a column; warp w sweeps
// i-chunk. AW bounded, no shift needed.
// ---------------------------------------------------------------------------
__global__ void __launch_bounds__(1024, 2) k_colstats() {
    __shared__ float sMrg[32][33];
    int b = blockIdx.x;
    int lane = threadIdx.x & 31, w = threadIdx.x >> 5;
    int col = blockIdx.y * 32 + lane;

    float4 U = g_jRec[b][col][0];
    float4 T = g_jRec[b][col][1];
    const float4* I0 = &g_iRec[b][w * 128][0];

    float acc = 0.f;
    #pragma unroll 2
    for (int k = 0; k < 128; k++) {
        float4 A = __ldg(I0 + k * 2);
        float4 F = __ldg(I0 + k * 2 + 1);
        float nL = -C25F - F.w;
        float d = fmaf(A.x, U.x, fmaf(A.y, U.y, A.z * U.z));
        float q = fmaxf(fmaf(-d, d, A.w), 0.f);
        float wgt = 1.f - ex2f(fmaf(sqapx(q), C50F, nL));
        float a2 = fmaf(F.x, T.x, fmaf(F.y, T.y, F.z * T.z));
        acc += ex2f(a2 * wgt);
    }
    sMrg[lane][w] = acc;
    __syncthreads();
    if (w == 0) {
        float S = 0.f;
        #pragma unroll
        for (int k = 0; k < 32; k++) S += sMrg[lane][k];
        ((float*)&g_jRec[b][col][0])[3] = log2f(S);
    }
}

// ---------------------------------------------------------------------------
// Pass 3: out[b,i,:] = sum_j exp2(AW2_ij - LSEcol2_j) * fs[:,j].
// Lane owns a row; warp w sweeps j-chunk; thread-private accumulators.
// ---------------------------------------------------------------------------
__global__ void __launch_bounds__(1024, 2) k_out(float* __restrict__ out) {
    __shared__ float s0[32][33], s1[32][33], s2[32][33];
    int b = blockIdx.x;
    int lane = threadIdx.x & 31, w = threadIdx.x >> 5;
    int row = blockIdx.y * 32 + lane;

    float4 A = g_iRec[b][row][0];
    float4 F = g_iRec[b][row][1];
    float nL = -C25F - F.w;
    const float4* J0 = &g_jRec[b][w * 128][0];

    float o0 = 0.f, o1 = 0.f, o2 = 0.f;
    #pragma unroll 2
    for (int k = 0; k < 128; k++) {
        float4 U = __ldg(J0 + k * 3);       // u, LSEcol2
        float4 T = __ldg(J0 + k * 3 + 1);   // ft * log2e
        float4 S = __ldg(J0 + k * 3 + 2);   // fs_j
        float d = fmaf(A.x, U.x, fmaf(A.y, U.y, A.z * U.z));
        float q = fmaxf(fmaf(-d, d, A.w), 0.f);
        float e = ex2f(fmaf(sqapx(q), C50F, nL));
        float a2 = fmaf(F.x, T.x, fmaf(F.y, T.y, F.z * T.z));
        float p = ex2f(fmaf(a2, 1.f - e, -U.w));
        o0 = fmaf(p, S.x, o0);
        o1 = fmaf(p, S.y, o1);
        o2 = fmaf(p, S.z, o2);
    }
    s0[lane][w] = o0; s1[lane][w] = o1; s2[lane][w] = o2;
    __syncthreads();
    if (w == 0) {
        float v0 = 0.f, v1 = 0.f, v2 = 0.f;
        #pragma unroll
        for (int k = 0; k < 32; k++) { v0 += s0[lane][k]; v1 += s1[lane][k]; v2 += s2[lane][k]; }
        int base = b * NPIX * 3 + row * 3;
        out[base]     = v0;
        out[base + 1] = v1;
        out[base + 2] = v2;
    }
}

// ---------------------------------------------------------------------------
extern "C" void kernel_launch(void* const* d_in, const int* in_sizes, int n_in,
                              void* d_out, int out_size) {
    const float* f_tar = (const float*)d_in[0];
    const float* f_src = (const float*)d_in[1];
    const float* Km    = (const float*)d_in[2];
    const float* Rm    = (const float*)d_in[3];
    const float* tv    = (const float*)d_in[4];
    float* out = (float*)d_out;

    k_pre<<<BT, 256>>>(f_tar, f_src, Km, Rm, tv);
    k_rowstats<<<dim3(BT, NPIX/32), 1024>>>();
    k_colstats<<<dim3(BT, NPIX/32), 1024>>>();
    k_out<<<dim3(BT, NPIX/32), 1024>>>(out);
}

// round 4
// speedup vs baseline: 1.1731x; 1.1731x over previous
#include <cuda_runtime.h>

#define NPIX 4096
#define BT 2

// 50*log2(e), 25*log2(e), log2(e)
#define C50F   72.13475204444817f
#define C25F   36.067376022224085f
#define CL2E   1.4426950408889634f

// ---------------------------------------------------------------------------
// Scratch (device globals)
// ---------------------------------------------------------------------------
__device__ float4 g_u4 [BT][NPIX];            // (u0,u1,u2,-)       for rowstats
__device__ float4 g_iA [BT][NPIX];            // (a0,a1,a2,|a|^2)
__device__ float4 g_iF [BT][NPIX];            // (fs0,fs1,fs2, cLrow = C25+L2row)
__device__ float4 g_jU [BT][NPIX];            // (u0,u1,u2, LSEcol2)
__device__ float4 g_jT [BT][NPIX];            // (ft*log2e x3, -)
__device__ float4 g_jS [BT][NPIX];            // (fs x3, -)
__device__ float  g_rmin [BT][NPIX];          // min over j of (a.u)^2
__device__ float  g_rpart[4][BT][NPIX];       // row LSE partial sums
__device__ float  g_cpart[4][BT][NPIX];       // col sum partials
__device__ float4 g_opart[4][BT][NPIX];       // output partials

// ---------------------------------------------------------------------------
__device__ __forceinline__ float ex2f(float x) {
    float y; asm("ex2.approx.ftz.f32 %0, %1;" : "=f"(y) : "f"(x)); return y;
}
__device__ __forceinline__ float sqapx(float x) {
    float y; asm("sqrt.approx.ftz.f32 %0, %1;" : "=f"(y) : "f"(x)); return y;
}

// ---------------------------------------------------------------------------
// Precompute per-i / per-j records (tiny; double precision for geometry)
// ---------------------------------------------------------------------------
__global__ void k_pre(const float* __restrict__ f_tar, const float* __restrict__ f_src,
                      const float* __restrict__ Km, const float* __restrict__ Rm,
                      const float* __restrict__ tv) {
    int b = blockIdx.x;
    double Kd[9], Rd[9], td[3];
    #pragma unroll
    for (int m = 0; m < 9; m++) { Kd[m] = (double)Km[b*9+m]; Rd[m] = (double)Rm[b*9+m]; }
    #pragma unroll
    for (int m = 0; m < 3; m++) td[m] = (double)tv[b*3+m];

    double c00 = Kd[4]*Kd[8] - Kd[5]*Kd[7];
    double c10 = Kd[5]*Kd[6] - Kd[3]*Kd[8];
    double c20 = Kd[3]*Kd[7] - Kd[4]*Kd[6];
    double det = Kd[0]*c00 + Kd[1]*c10 + Kd[2]*c20;
    double id  = 1.0 / det;
    double Ki[9];
    Ki[0] = c00*id; Ki[1] = (Kd[2]*Kd[7]-Kd[1]*Kd[8])*id; Ki[2] = (Kd[1]*Kd[5]-Kd[2]*Kd[4])*id;
    Ki[3] = c10*id; Ki[4] = (Kd[0]*Kd[8]-Kd[2]*Kd[6])*id; Ki[5] = (Kd[2]*Kd[3]-Kd[0]*Kd[5])*id;
    Ki[6] = c20*id; Ki[7] = (Kd[1]*Kd[6]-Kd[0]*Kd[7])*id; Ki[8] = (Kd[0]*Kd[4]-Kd[1]*Kd[3])*id;

    double o0 = Kd[0]*td[0] + Kd[1]*td[1] + Kd[2]*td[2];
    double o1 = Kd[3]*td[0] + Kd[4]*td[1] + Kd[5]*td[2];
    double o2 = Kd[6]*td[0] + Kd[7]*td[1] + Kd[8]*td[2];
    float of0 = (float)o0, of1 = (float)o1, of2 = (float)o2;

    const float* fs = f_src + b*3*NPIX;
    const float* ft = f_tar + b*3*NPIX;

    for (int j = threadIdx.x; j < NPIX; j += blockDim.x) {
        double px = (double)(j >> 6), py = (double)(j & 63);
        double ca = Ki[0]*px + Ki[1]*py + Ki[2];
        double cb = Ki[3]*px + Ki[4]*py + Ki[5];
        double cc = Ki[6]*px + Ki[7]*py + Ki[8];
        double ra = Rd[0]*ca + Rd[1]*cb + Rd[2]*cc + td[0];
        double rb = Rd[3]*ca + Rd[4]*cb + Rd[5]*cc + td[1];
        double rc = Rd[6]*ca + Rd[7]*cb + Rd[8]*cc + td[2];
        double da = Kd[0]*ra + Kd[1]*rb + Kd[2]*rc - o0;
        double db = Kd[3]*ra + Kd[4]*rb + Kd[5]*rc - o1;
        double dc = Kd[6]*ra + Kd[7]*rb + Kd[8]*rc - o2;
        double inv = 1.0 / sqrt(da*da + db*db + dc*dc);
        float u0 = (float)(da*inv), u1 = (float)(db*inv), u2 = (float)(dc*inv);

        float t0 = ft[j], t1 = ft[NPIX + j], t2 = ft[2*NPIX + j];
        float s0 = fs[j], s1 = fs[NPIX + j], s2 = fs[2*NPIX + j];
        g_u4[b][j] = make_float4(u0, u1, u2, 0.f);
        g_jU[b][j] = make_float4(u0, u1, u2, 0.f);
        g_jT[b][j] = make_float4(t0*CL2E, t1*CL2E, t2*CL2E, 0.f);
        g_jS[b][j] = make_float4(s0, s1, s2, 0.f);

        float a0 = s0 - of0, a1 = s1 - of1, a2 = s2 - of2;
        float na2 = (float)((double)a0*a0 + (double)a1*a1 + (double)a2*a2);
        g_iA[b][j] = make_float4(a0, a1, a2, na2);
        g_iF[b][j] = make_float4(s0, s1, s2, 0.f);
        g_rmin[b][j] = 3.0e38f;
    }
}

// ---------------------------------------------------------------------------
// rowA: min over j of (a_i . u_j)^2  (exact row max of d, no MUFU).
// Block 512 = 16 warps; lane owns rows (base+lane, base+lane+32); warp w sweeps
// j-chunk of 64 within the z-th quarter. atomicMin (exact) combines blocks.
// ---------------------------------------------------------------------------
__global__ void __launch_bounds__(512, 3) k_rowA() {
    __shared__ float sm[64][17];
    int b = blockIdx.x;
    int lane = threadIdx.x & 31, w = threadIdx.x >> 5;
    int rbase = blockIdx.y * 64;
    float4 A0 = g_iA[b][rbase + lane];
    float4 A1 = g_iA[b][rbase + lane + 32];
    const float4* U0 = &g_u4[b][blockIdx.z * 1024 + w * 64];

    float m0 = 3.4e38f, m1 = 3.4e38f;
    #pragma unroll 4
    for (int k = 0; k < 64; k++) {
        float4 U = __ldg(U0 + k);
        float d0 = fmaf(A0.x, U.x, fmaf(A0.y, U.y, A0.z * U.z));
        float d1 = fmaf(A1.x, U.x, fmaf(A1.y, U.y, A1.z * U.z));
        m0 = fminf(m0, d0 * d0);
        m1 = fminf(m1, d1 * d1);
    }
    sm[lane][w] = m0; sm[lane + 32][w] = m1;
    __syncthreads();
    if (threadIdx.x < 64) {
        float m = 3.4e38f;
        #pragma unroll
        for (int k = 0; k < 16; k++) m = fminf(m, sm[threadIdx.x][k]);
        atomicMin((int*)&g_rmin[b][rbase + threadIdx.x], __float_as_int(m));
    }
}

// ---------------------------------------------------------------------------
// rowB: partial sums of ex2(50log2e*d - cM) over j-quarter.
// ---------------------------------------------------------------------------
__global__ void __launch_bounds__(512, 3) k_rowB() {
    __shared__ float sm[64][17];
    int b = blockIdx.x;
    int lane = threadIdx.x & 31, w = threadIdx.x >> 5;
    int rbase = blockIdx.y * 64;
    float4 A0 = g_iA[b][rbase + lane];
    float4 A1 = g_iA[b][rbase + lane + 32];
    float cM0 = sqapx(fmaxf(A0.w - g_rmin[b][rbase + lane], 0.f)) * C50F;
    float cM1 = sqapx(fmaxf(A1.w - g_rmin[b][rbase + lane + 32], 0.f)) * C50F;
    const float4* U0 = &g_u4[b][blockIdx.z * 1024 + w * 64];

    float s0 = 0.f, s1 = 0.f;
    #pragma unroll 4
    for (int k = 0; k < 64; k++) {
        float4 U = __ldg(U0 + k);
        float d0 = fmaf(A0.x, U.x, fmaf(A0.y, U.y, A0.z * U.z));
        float q0 = fmaxf(fmaf(-d0, d0, A0.w), 0.f);
        s0 += ex2f(fmaf(sqapx(q0), C50F, -cM0));
        float d1 = fmaf(A1.x, U.x, fmaf(A1.y, U.y, A1.z * U.z));
        float q1 = fmaxf(fmaf(-d1, d1, A1.w), 0.f);
        s1 += ex2f(fmaf(sqapx(q1), C50F, -cM1));
    }
    sm[lane][w] = s0; sm[lane + 32][w] = s1;
    __syncthreads();
    if (threadIdx.x < 64) {
        float s = 0.f;
        #pragma unroll
        for (int k = 0; k < 16; k++) s += sm[threadIdx.x][k];
        g_rpart[blockIdx.z][b][rbase + threadIdx.x] = s;
    }
}

// rowcomb: cLrow = C25 + L2row = cM + log2(S)
__global__ void k_rowcomb() {
    int b = blockIdx.x;
    int row = blockIdx.y * 256 + threadIdx.x;
    float Aw = g_iA[b][row].w;
    float cM = sqapx(fmaxf(Aw - g_rmin[b][row], 0.f)) * C50F;
    float S = g_rpart[0][b][row] + g_rpart[1][b][row] + g_rpart[2][b][row] + g_rpart[3][b][row];
    ((float*)&g_iF[b][row])[3] = cM + log2f(S);
}

// ---------------------------------------------------------------------------
// colstats: partial column sums of ex2(a2*(1-e)) over i-quarter.
// Lane owns cols (base+lane, base+lane+32); warp w sweeps i-chunk of 64.
// ---------------------------------------------------------------------------
__global__ void __launch_bounds__(512, 3) k_col() {
    __shared__ float sm[64][17];
    int b = blockIdx.x;
    int lane = threadIdx.x & 31, w = threadIdx.x >> 5;
    int cbase = blockIdx.y * 64;
    float4 Ua = g_jU[b][cbase + lane];
    float4 Ta = g_jT[b][cbase + lane];
    float4 Ub = g_jU[b][cbase + lane + 32];
    float4 Tb = g_jT[b][cbase + lane + 32];
    const float4* I0 = &g_iA[b][blockIdx.z * 1024 + w * 64];
    const float4* F0 = &g_iF[b][blockIdx.z * 1024 + w * 64];

    float acc0 = 0.f, acc1 = 0.f;
    #pragma unroll 2
    for (int k = 0; k < 64; k++) {
        float4 A = __ldg(I0 + k);
        float4 F = __ldg(F0 + k);
        float nL = -F.w;
        float d0 = fmaf(A.x, Ua.x, fmaf(A.y, Ua.y, A.z * Ua.z));
        float q0 = fmaxf(fmaf(-d0, d0, A.w), 0.f);
        float e0 = ex2f(fmaf(sqapx(q0), C50F, nL));
        float a0 = fmaf(F.x, Ta.x, fmaf(F.y, Ta.y, F.z * Ta.z));
        acc0 += ex2f(fmaf(-a0, e0, a0));
        float d1 = fmaf(A.x, Ub.x, fmaf(A.y, Ub.y, A.z * Ub.z));
        float q1 = fmaxf(fmaf(-d1, d1, A.w), 0.f);
        float e1 = ex2f(fmaf(sqapx(q1), C50F, nL));
        float a1 = fmaf(F.x, Tb.x, fmaf(F.y, Tb.y, F.z * Tb.z));
        acc1 += ex2f(fmaf(-a1, e1, a1));
    }
    sm[lane][w] = acc0; sm[lane + 32][w] = acc1;
    __syncthreads();
    if (threadIdx.x < 64) {
        float s = 0.f;
        #pragma unroll
        for (int k = 0; k < 16; k++) s += sm[threadIdx.x][k];
        g_cpart[blockIdx.z][b][cbase + threadIdx.x] = s;
    }
}

// colcomb: LSEcol2 = log2(sum)
__global__ void k_colcomb() {
    int b = blockIdx.x;
    int col = blockIdx.y * 256 + threadIdx.x;
    float S = g_cpart[0][b][col] + g_cpart[1][b][col] + g_cpart[2][b][col] + g_cpart[3][b][col];
    ((float*)&g_jU[b][col])[3] = log2f(S);
}

// ---------------------------------------------------------------------------
// kout: partial out[i,:] = sum_j ex2(a2*(1-e) - LSEcol2_j) * fs_j over j-quarter.
// ---------------------------------------------------------------------------
__global__ void __launch_bounds__(512, 2) k_out() {
    __shared__ float sa[64][17], sb[64][17], sc[64][17];
    int b = blockIdx.x;
    int lane = threadIdx.x & 31, w = threadIdx.x >> 5;
    int rbase = blockIdx.y * 64;
    float4 A0 = g_iA[b][rbase + lane];
    float4 F0 = g_iF[b][rbase + lane];
    float4 A1 = g_iA[b][rbase + lane + 32];
    float4 F1 = g_iF[b][rbase + lane + 32];
    float nL0 = -F0.w, nL1 = -F1.w;
    int j0 = blockIdx.z * 1024 + w * 64;
    const float4* PU = &g_jU[b][j0];
    const float4* PT = &g_jT[b][j0];
    const float4* PS = &g_jS[b][j0];

    float x0 = 0.f, y0 = 0.f, z0 = 0.f;
    float x1 = 0.f, y1 = 0.f, z1 = 0.f;
    #pragma unroll 2
    for (int k = 0; k < 64; k++) {
        float4 U = __ldg(PU + k);
        float4 T = __ldg(PT + k);
        float4 S = __ldg(PS + k);
        float d0 = fmaf(A0.x, U.x, fmaf(A0.y, U.y, A0.z * U.z));
        float q0 = fmaxf(fmaf(-d0, d0, A0.w), 0.f);
        float e0 = ex2f(fmaf(sqapx(q0), C50F, nL0));
        float a0 = fmaf(F0.x, T.x, fmaf(F0.y, T.y, F0.z * T.z));
        float p0 = ex2f(fmaf(-a0, e0, a0 - U.w));
        x0 = fmaf(p0, S.x, x0); y0 = fmaf(p0, S.y, y0); z0 = fmaf(p0, S.z, z0);
        float d1 = fmaf(A1.x, U.x, fmaf(A1.y, U.y, A1.z * U.z));
        float q1 = fmaxf(fmaf(-d1, d1, A1.w), 0.f);
        float e1 = ex2f(fmaf(sqapx(q1), C50F, nL1));
        float a1 = fmaf(F1.x, T.x, fmaf(F1.y, T.y, F1.z * T.z));
        float p1 = ex2f(fmaf(-a1, e1, a1 - U.w));
        x1 = fmaf(p1, S.x, x1); y1 = fmaf(p1, S.y, y1); z1 = fmaf(p1, S.z, z1);
    }
    sa[lane][w] = x0; sb[lane][w] = y0; sc[lane][w] = z0;
    sa[lane+32][w] = x1; sb[lane+32][w] = y1; sc[lane+32][w] = z1;
    __syncthreads();
    if (threadIdx.x < 64) {
        float v0 = 0.f, v1 = 0.f, v2 = 0.f;
        #pragma unroll
        for (int k = 0; k < 16; k++) {
            v0 += sa[threadIdx.x][k]; v1 += sb[threadIdx.x][k]; v2 += sc[threadIdx.x][k];
        }
        g_opart[blockIdx.z][b][rbase + threadIdx.x] = make_float4(v0, v1, v2, 0.f);
    }
}

// outcomb: sum 4 partials -> out (B,N,C layout)
__global__ void k_outcomb(float* __restrict__ out) {
    int b = blockIdx.x;
    int row = blockIdx.y * 256 + threadIdx.x;
    float4 p0 = g_opart[0][b][row], p1 = g_opart[1][b][row];
    float4 p2 = g_opart[2][b][row], p3 = g_opart[3][b][row];
    int base = b * NPIX * 3 + row * 3;
    out[base]     = p0.x + p1.x + p2.x + p3.x;
    out[base + 1] = p0.y + p1.y + p2.y + p3.y;
    out[base + 2] = p0.z + p1.z + p2.z + p3.z;
}

// ---------------------------------------------------------------------------
extern "C" void kernel_launch(void* const* d_in, const int* in_sizes, int n_in,
                              void* d_out, int out_size) {
    const float* f_tar = (const float*)d_in[0];
    const float* f_src = (const float*)d_in[1];
    const float* Km    = (const float*)d_in[2];
    const float* Rm    = (const float*)d_in[3];
    const float* tv    = (const float*)d_in[4];
    float* out = (float*)d_out;

    dim3 gridN2(BT, NPIX/64, 4);
    dim3 gridC(BT, NPIX/256);

    k_pre    <<<BT, 256>>>(f_tar, f_src, Km, Rm, tv);
    k_rowA   <<<gridN2, 512>>>();
    k_rowB   <<<gridN2, 512>>>();
    k_rowcomb<<<gridC, 256>>>();
    k_col    <<<gridN2, 512>>>();
    k_colcomb<<<gridC, 256>>>();
    k_out    <<<gridN2, 512>>>();
    k_outcomb<<<gridC, 256>>>(out);
}